// round 1
// baseline (speedup 1.0000x reference)
#include <cuda_runtime.h>
#include <math.h>

#define BB 2
#define CC 128
#define TT 512
#define FF 64
#define HH 32
#define DD 32

// -------- scratch (device globals: allocation-free) --------
__device__ float g_xm1[BB*HH*TT*FF];   // (b,h,t,f)
__device__ float g_xf1[BB*HH*TT*FF];   // (b,h,t,f)
__device__ float g_corr[BB*HH*TT*DD];  // (b,h,t,d)
__device__ float g_w[BB*TT*DD];        // (b,t,d) softmax weights

// ============================================================
// K1: projection  out[b,h,t,f] = sum_c x[b,c,t,f]*w[c,h] + bias[h]
// one thread per (b,t,f), 32 h-accumulators, w in smem (float4 reads)
// ============================================================
__global__ void proj_kernel(const float* __restrict__ x,
                            const float* __restrict__ w,
                            const float* __restrict__ bias,
                            int which)   // 0 -> g_xm1, 1 -> g_xf1
{
    __shared__ float ws[CC*HH];   // [c][h], h contiguous
    int tid = threadIdx.x;
    for (int i = tid; i < CC*HH; i += 256) ws[i] = w[i];
    __syncthreads();

    int gid = blockIdx.x * 256 + tid;
    int f = gid % FF;
    int t = (gid / FF) % TT;
    int b = gid / (FF*TT);

    float acc[HH];
#pragma unroll
    for (int h = 0; h < HH; h++) acc[h] = 0.f;

    const float* xp = x + ((size_t)b*CC*TT + t)*FF + f;  // +c*T*F per channel
#pragma unroll 4
    for (int c = 0; c < CC; c++) {
        float v = xp[(size_t)c*TT*FF];
        const float4* wr = (const float4*)(ws + c*HH);
#pragma unroll
        for (int h4 = 0; h4 < HH/4; h4++) {
            float4 wv = wr[h4];
            acc[h4*4+0] = fmaf(v, wv.x, acc[h4*4+0]);
            acc[h4*4+1] = fmaf(v, wv.y, acc[h4*4+1]);
            acc[h4*4+2] = fmaf(v, wv.z, acc[h4*4+2]);
            acc[h4*4+3] = fmaf(v, wv.w, acc[h4*4+3]);
        }
    }

    float* out = which ? g_xf1 : g_xm1;
#pragma unroll
    for (int h = 0; h < HH; h++)
        out[((size_t)(b*HH+h)*TT + t)*FF + f] = acc[h] + bias[h];
}

// ============================================================
// K2: banded correlation
// corr[b,h,t,d] = sum_f xm1[b,h,t,f] * xf1[b,h,t+d-31,f]   (0 if t+d<31)
// block = (t-tile of 64) x h x b ; tiles in smem
// ============================================================
#define K2T 64
__global__ void corr_kernel()
{
    __shared__ float sm[K2T][FF];          // xm1 rows t0..t0+63 (broadcast reads)
    __shared__ float sf[K2T+31][FF+1];     // xf1 rows t0-31..t0+63, stride 65 (conflict-free)

    int b = blockIdx.z, h = blockIdx.y, t0 = blockIdx.x * K2T;
    int tid = threadIdx.x;   // 256

    const float* xmp = g_xm1 + ((size_t)(b*HH+h)*TT)*FF;
    const float* xfp = g_xf1 + ((size_t)(b*HH+h)*TT)*FF;

    for (int i = tid; i < K2T*FF; i += 256) {
        int r = i / FF, fc = i % FF;
        sm[r][fc] = xmp[(size_t)(t0+r)*FF + fc];
    }
    for (int i = tid; i < (K2T+31)*FF; i += 256) {
        int r = i / FF, fc = i % FF;
        int tt = t0 + r - 31;
        sf[r][fc] = (tt >= 0) ? xfp[(size_t)tt*FF + fc] : 0.f;
    }
    __syncthreads();

    int d   = tid & 31;        // warp lanes span d -> coalesced stores
    int tl0 = tid >> 5;        // 0..7
#pragma unroll
    for (int j = 0; j < 8; j++) {
        int tl = tl0*8 + j;    // 0..63
        const float* a  = sm[tl];
        const float* bb = sf[tl + d];
        float acc = 0.f;
#pragma unroll
        for (int fc = 0; fc < FF; fc++)
            acc = fmaf(a[fc], bb[fc], acc);
        g_corr[((size_t)(b*HH+h)*TT + (t0+tl))*DD + d] = acc;
    }
}

// ============================================================
// K3: 5x3 conv over (t,d) reduced over h, + bias, mask, softmax over d
// block = 8 t x 32 d (lane = d), warp softmax
// ============================================================
__global__ void conv_softmax_kernel(const float* __restrict__ wc,
                                    const float* __restrict__ bc)
{
    __shared__ float wcs[HH*15];
    int tid = threadIdx.x;  // 256
    for (int i = tid; i < HH*15; i += 256) wcs[i] = wc[i];
    __syncthreads();

    int d  = tid & 31;
    int tl = tid >> 5;
    int t  = blockIdx.x * 8 + tl;
    int b  = blockIdx.y;

    float acc = bc[0];
    for (int h = 0; h < HH; h++) {
        const float* cp = g_corr + ((size_t)(b*HH+h)*TT)*DD;
        const float* wh = wcs + h*15;
#pragma unroll
        for (int kh = 0; kh < 5; kh++) {
            int tt = t + kh - 3;
            if (tt < 0 || tt >= TT) continue;
#pragma unroll
            for (int kw = 0; kw < 3; kw++) {
                int dd = d + kw - 1;
                if (dd < 0 || dd >= DD) continue;
                acc = fmaf(cp[(size_t)tt*DD + dd], wh[kh*3 + kw], acc);
            }
        }
    }

    if (t + d < DD - 1) acc = -1e13f;   // NEG_INF mask (replace)

    // softmax over d = warp lanes
    float m = acc;
#pragma unroll
    for (int o = 16; o; o >>= 1) m = fmaxf(m, __shfl_xor_sync(0xffffffffu, m, o));
    float e = expf(acc - m);
    float s = e;
#pragma unroll
    for (int o = 16; o; o >>= 1) s += __shfl_xor_sync(0xffffffffu, s, o);

    g_w[((size_t)b*TT + t)*DD + d] = e / s;
}

// ============================================================
// K4: out[b,c,t,f] = sum_d w[b,t,d] * xf[b,c,t+d-31,f]
// block = (b,c,t-tile of 64), 512 threads: lane f, 8 t per thread.
// Loop over source rows: each xf value loaded once, reused for 8 outputs.
// ============================================================
#define K4T 64
__global__ void out_kernel(const float* __restrict__ xf, float* __restrict__ out)
{
    __shared__ float sx[K4T+31][FF];   // xf rows t0-31 .. t0+63
    __shared__ float sw[K4T][DD];      // softmax weights rows t0..t0+63

    int b = blockIdx.z, c = blockIdx.y, t0 = blockIdx.x * K4T;
    int tid = threadIdx.x;  // 512

    const float* xp = xf + ((size_t)(b*CC + c)*TT)*FF;
    for (int i = tid; i < (K4T+31)*FF; i += 512) {
        int r = i / FF, fc = i % FF;
        int tt = t0 + r - 31;
        sx[r][fc] = (tt >= 0) ? xp[(size_t)tt*FF + fc] : 0.f;
    }
    const float* wp = g_w + ((size_t)b*TT + t0)*DD;
    for (int i = tid; i < K4T*DD; i += 512) sw[i/DD][i%DD] = wp[i];
    __syncthreads();

    int f  = tid & 63;
    int tb = (tid >> 6) * 8;     // this thread's t_local range [tb, tb+8)

    float acc[8];
#pragma unroll
    for (int i = 0; i < 8; i++) acc[i] = 0.f;

    // sx row r serves output t_local=tb+i with d = r - (tb+i)
#pragma unroll 1
    for (int r = tb; r < tb + 39; r++) {
        float xv = sx[r][f];
#pragma unroll
        for (int i = 0; i < 8; i++) {
            int d = r - (tb + i);
            if (d >= 0 && d < DD)
                acc[i] = fmaf(sw[tb + i][d], xv, acc[i]);
        }
    }

    float* op = out + ((size_t)(b*CC + c)*TT)*FF;
#pragma unroll
    for (int i = 0; i < 8; i++)
        op[(size_t)(t0 + tb + i)*FF + f] = acc[i];
}

// ============================================================
extern "C" void kernel_launch(void* const* d_in, const int* in_sizes, int n_in,
                              void* d_out, int out_size)
{
    const float* xm = (const float*)d_in[0];
    const float* xf = (const float*)d_in[1];
    const float* w1 = (const float*)d_in[2];
    const float* b1 = (const float*)d_in[3];
    const float* w2 = (const float*)d_in[4];
    const float* b2 = (const float*)d_in[5];
    const float* wc = (const float*)d_in[6];
    const float* bc = (const float*)d_in[7];
    float* out = (float*)d_out;

    (void)in_sizes; (void)n_in; (void)out_size;

    // K1: projections (two launches, independent)
    proj_kernel<<<(BB*TT*FF)/256, 256>>>(xm, w1, b1, 0);
    proj_kernel<<<(BB*TT*FF)/256, 256>>>(xf, w2, b2, 1);

    // K2: banded correlation
    dim3 g2(TT/K2T, HH, BB);
    corr_kernel<<<g2, 256>>>();

    // K3: conv + mask + softmax
    dim3 g3(TT/8, BB);
    conv_softmax_kernel<<<g3, 256>>>(wc, bc);

    // K4: weighted window gather
    dim3 g4(TT/K4T, CC, BB);
    out_kernel<<<g4, 512>>>(xf, out);
}

// round 2
// speedup vs baseline: 1.0407x; 1.0407x over previous
#include <cuda_runtime.h>
#include <math.h>

#define BB 2
#define CC 128
#define TT 512
#define FF 64
#define HH 32
#define DD 32

typedef unsigned long long u64;

// -------- f32x2 packed-FMA helpers (sm_103a) --------
__device__ __forceinline__ u64 pack2(float lo, float hi) {
    u64 r; asm("mov.b64 %0,{%1,%2};" : "=l"(r) : "f"(lo), "f"(hi)); return r;
}
__device__ __forceinline__ void unpack2(u64 v, float& a, float& b) {
    asm("mov.b64 {%0,%1},%2;" : "=f"(a), "=f"(b) : "l"(v));
}
__device__ __forceinline__ u64 fma2(u64 a, u64 b, u64 c) {
    u64 d; asm("fma.rn.f32x2 %0,%1,%2,%3;" : "=l"(d) : "l"(a), "l"(b), "l"(c)); return d;
}

// -------- scratch (device globals: allocation-free) --------
__device__ float g_xm1[BB*HH*TT*FF];   // (b,h,t,f)
__device__ float g_xf1[BB*HH*TT*FF];   // (b,h,t,f)
__device__ float g_corr[BB*HH*TT*DD];  // (b,h,t,d)
__device__ float g_w[BB*TT*DD];        // (b,t,d) softmax weights

// ============================================================
// K1: projection  out[b,h,t,f] = sum_c x[b,c,t,f]*w[c,h] + bias[h]
// one thread per (b,t,f); 16 f32x2 accumulators over h-pairs.
// ============================================================
__global__ void proj_kernel(const float* __restrict__ x,
                            const float* __restrict__ w,
                            const float* __restrict__ bias,
                            int which)   // 0 -> g_xm1, 1 -> g_xf1
{
    __shared__ float ws[CC*HH];   // [c][h], h contiguous -> natural h-pairs
    __shared__ float bs[HH];
    int tid = threadIdx.x;
    for (int i = tid; i < CC*HH; i += 256) ws[i] = w[i];
    if (tid < HH) bs[tid] = bias[tid];
    __syncthreads();

    int gid = blockIdx.x * 256 + tid;
    int f = gid & 63;
    int t = (gid >> 6) & 511;
    int b = gid >> 15;

    u64 acc[HH/2];
#pragma unroll
    for (int i = 0; i < HH/2; i++) acc[i] = 0ull;   // (0.f,0.f)

    const float* xp = x + ((size_t)b*CC*TT + t)*FF + f;
#pragma unroll 1
    for (int c0 = 0; c0 < CC; c0 += 8) {
        float v[8];
#pragma unroll
        for (int j = 0; j < 8; j++) v[j] = xp[(size_t)(c0+j)*TT*FF];
#pragma unroll
        for (int j = 0; j < 8; j++) {
            u64 vp = pack2(v[j], v[j]);
            const u64* wp = (const u64*)(ws + (c0+j)*HH);
#pragma unroll
            for (int hp = 0; hp < HH/2; hp++)
                acc[hp] = fma2(vp, wp[hp], acc[hp]);
        }
    }

    float* out = which ? g_xf1 : g_xm1;
#pragma unroll
    for (int hp = 0; hp < HH/2; hp++) {
        float a0, a1; unpack2(acc[hp], a0, a1);
        out[((size_t)(b*HH + 2*hp  )*TT + t)*FF + f] = a0 + bs[2*hp];
        out[((size_t)(b*HH + 2*hp+1)*TT + t)*FF + f] = a1 + bs[2*hp+1];
    }
}

// ============================================================
// K2: banded correlation (register-tiled band-GEMM)
// corr[b,h,t,d] = sum_f xm1[b,h,t,f] * xf1[b,h,t+d-31,f]   (0-padded)
// block = (t-tile 64, h, b), 128 threads, 4x4 (t,d) tile/thread,
// f32x2 over f-pairs. smem stride 70 floats: 8B-aligned rows,
// conflict-free cross-row B loads.
// ============================================================
#define K2T 64
#define K2S 70
__global__ void corr_kernel()
{
    __shared__ float sm[K2T*K2S];         // xm1 rows t0..t0+63
    __shared__ float sf[(K2T+31)*K2S];    // xf1 rows t0-31..t0+63

    int b = blockIdx.z, h = blockIdx.y, t0 = blockIdx.x * K2T;
    int tid = threadIdx.x;   // 128

    const float* xmp = g_xm1 + ((size_t)(b*HH+h)*TT)*FF;
    const float* xfp = g_xf1 + ((size_t)(b*HH+h)*TT)*FF;

    for (int i = tid; i < K2T*FF; i += 128) {
        int r = i >> 6, fc = i & 63;
        sm[r*K2S + fc] = xmp[(size_t)(t0+r)*FF + fc];
    }
    for (int i = tid; i < (K2T+31)*FF; i += 128) {
        int r = i / 64, fc = i & 63;
        int tt = t0 + r - 31;
        sf[r*K2S + fc] = (tt >= 0) ? xfp[(size_t)tt*FF + fc] : 0.f;
    }
    __syncthreads();

    int tl0 = (tid >> 3) << 2;   // 0,4,...,60
    int d0  = (tid & 7)  << 2;   // 0,4,...,28

    u64 acc[4][4];
#pragma unroll
    for (int i = 0; i < 4; i++)
#pragma unroll
        for (int j = 0; j < 4; j++) acc[i][j] = 0ull;

#pragma unroll 2
    for (int fcp = 0; fcp < FF/2; fcp++) {
        u64 a[4], br[7];
#pragma unroll
        for (int i = 0; i < 4; i++)
            a[i] = *(const u64*)(sm + (tl0+i)*K2S + fcp*2);
#pragma unroll
        for (int k = 0; k < 7; k++)
            br[k] = *(const u64*)(sf + (tl0+d0+k)*K2S + fcp*2);
#pragma unroll
        for (int i = 0; i < 4; i++)
#pragma unroll
            for (int j = 0; j < 4; j++)
                acc[i][j] = fma2(a[i], br[i+j], acc[i][j]);
    }

#pragma unroll
    for (int i = 0; i < 4; i++) {
        float4 v;
        float x0, x1;
        unpack2(acc[i][0], x0, x1); v.x = x0 + x1;
        unpack2(acc[i][1], x0, x1); v.y = x0 + x1;
        unpack2(acc[i][2], x0, x1); v.z = x0 + x1;
        unpack2(acc[i][3], x0, x1); v.w = x0 + x1;
        *(float4*)(g_corr + (((size_t)(b*HH+h)*TT + (t0+tl0+i))*DD + d0)) = v;
    }
}

// ============================================================
// K3: 5x3 conv over (t,d) reduced over h, + bias, mask, softmax over d
// block = (16-t tile, b), 256 threads. Per-h corr tile (22x34 with conv
// halo, zero-padded) staged in ping-pong smem; lane = d; warp handles 2 t.
// ============================================================
__global__ void conv_softmax_kernel(const float* __restrict__ wc,
                                    const float* __restrict__ bc)
{
    __shared__ float sc[2][22*36];
    __shared__ float wcs[HH*15];
    int tid = threadIdx.x;  // 256
    int b = blockIdx.y, t0 = blockIdx.x * 16;

    for (int i = tid; i < HH*15; i += 256) wcs[i] = wc[i];

    // stage corr tile for head h into buffer buf
    const size_t base = (size_t)b*HH*TT*DD;
#define K3_LOAD(hh, buf)                                                 \
    {                                                                    \
        const float* cp = g_corr + base + (size_t)(hh)*TT*DD;            \
        for (int i = tid; i < 22*34; i += 256) {                         \
            int r = i / 34, col = i % 34;                                \
            int tt = t0 - 3 + r, dd2 = col - 1;                          \
            float v = 0.f;                                               \
            if (tt >= 0 && tt < TT && dd2 >= 0 && dd2 < DD)              \
                v = cp[(size_t)tt*DD + dd2];                             \
            sc[buf][r*36 + col] = v;                                     \
        }                                                                \
    }

    K3_LOAD(0, 0);
    __syncthreads();

    int d   = tid & 31;
    int wrp = tid >> 5;         // 0..7
    int i0 = wrp*2, i1 = wrp*2 + 1;   // two local t rows per warp

    float acc0 = 0.f, acc1 = 0.f;
    for (int h = 0; h < HH; h++) {
        if (h + 1 < HH) K3_LOAD(h + 1, (h + 1) & 1);
        const float* s  = sc[h & 1];
        const float* wv = wcs + h*15;
#pragma unroll
        for (int kh = 0; kh < 5; kh++) {
#pragma unroll
            for (int kw = 0; kw < 3; kw++) {
                float wt = wv[kh*3 + kw];
                acc0 = fmaf(s[(i0+kh)*36 + d + kw], wt, acc0);
                acc1 = fmaf(s[(i1+kh)*36 + d + kw], wt, acc1);
            }
        }
        __syncthreads();
    }

    float bcv = bc[0];
    acc0 += bcv; acc1 += bcv;
    int ta = t0 + i0, tb2 = t0 + i1;
    if (ta  + d < DD - 1) acc0 = -1e13f;
    if (tb2 + d < DD - 1) acc1 = -1e13f;

    // warp softmax over d for each of the two t rows
    float m0 = acc0, m1 = acc1;
#pragma unroll
    for (int o = 16; o; o >>= 1) {
        m0 = fmaxf(m0, __shfl_xor_sync(0xffffffffu, m0, o));
        m1 = fmaxf(m1, __shfl_xor_sync(0xffffffffu, m1, o));
    }
    float e0 = expf(acc0 - m0), e1 = expf(acc1 - m1);
    float s0 = e0, s1 = e1;
#pragma unroll
    for (int o = 16; o; o >>= 1) {
        s0 += __shfl_xor_sync(0xffffffffu, s0, o);
        s1 += __shfl_xor_sync(0xffffffffu, s1, o);
    }
    g_w[((size_t)b*TT + ta )*DD + d] = e0 / s0;
    g_w[((size_t)b*TT + tb2)*DD + d] = e1 / s1;
}

// ============================================================
// K4: out[b,c,t,f] = sum_d w[b,t,d] * xf[b,c,t+d-31,f]
// block = (64-t tile, c, b), 256 threads: lane = f-pair, 8 t/thread.
// f32x2 over f-pairs; weights pre-duplicated (w,w) in smem -> b-operand
// is a single broadcast LDS.64.
// ============================================================
#define K4T 64
__global__ void out_kernel(const float* __restrict__ xf, float* __restrict__ out)
{
    __shared__ float sx[(K4T+31)*FF];   // xf rows t0-31 .. t0+63
    __shared__ u64   swd[K4T*DD];       // duplicated weights (w,w)

    int b = blockIdx.z, c = blockIdx.y, t0 = blockIdx.x * K4T;
    int tid = threadIdx.x;  // 256

    const float* xp = xf + ((size_t)(b*CC + c)*TT)*FF;
    for (int i = tid; i < (K4T+31)*FF; i += 256) {
        int r = i >> 6;
        int tt = t0 + r - 31;
        sx[i] = (tt >= 0) ? xp[(size_t)tt*FF + (i & 63)] : 0.f;
    }
    const float* wp = g_w + ((size_t)b*TT + t0)*DD;
    for (int i = tid; i < K4T*DD; i += 256) {
        float v = wp[i];
        swd[i] = pack2(v, v);
    }
    __syncthreads();

    int f2 = tid & 31;           // f-pair index
    int tb = (tid >> 5) * 8;     // t_local range [tb, tb+8)

    u64 acc[8];
#pragma unroll
    for (int i = 0; i < 8; i++) acc[i] = 0ull;

#pragma unroll 1
    for (int r = tb; r < tb + 39; r++) {
        u64 a2 = *(const u64*)(sx + r*FF + f2*2);
#pragma unroll
        for (int i = 0; i < 8; i++) {
            int dd = r - tb - i;
            if (dd >= 0 && dd < DD)
                acc[i] = fma2(a2, swd[(tb+i)*DD + dd], acc[i]);
        }
    }

    float* op = out + ((size_t)(b*CC + c)*TT + (t0 + tb))*FF + f2*2;
#pragma unroll
    for (int i = 0; i < 8; i++) {
        float x0, x1; unpack2(acc[i], x0, x1);
        *(float2*)(op + (size_t)i*FF) = make_float2(x0, x1);
    }
}

// ============================================================
extern "C" void kernel_launch(void* const* d_in, const int* in_sizes, int n_in,
                              void* d_out, int out_size)
{
    const float* xm = (const float*)d_in[0];
    const float* xf = (const float*)d_in[1];
    const float* w1 = (const float*)d_in[2];
    const float* b1 = (const float*)d_in[3];
    const float* w2 = (const float*)d_in[4];
    const float* b2 = (const float*)d_in[5];
    const float* wc = (const float*)d_in[6];
    const float* bc = (const float*)d_in[7];
    float* out = (float*)d_out;

    (void)in_sizes; (void)n_in; (void)out_size;

    proj_kernel<<<(BB*TT*FF)/256, 256>>>(xm, w1, b1, 0);
    proj_kernel<<<(BB*TT*FF)/256, 256>>>(xf, w2, b2, 1);

    dim3 g2(TT/K2T, HH, BB);
    corr_kernel<<<g2, 128>>>();

    dim3 g3(TT/16, BB);
    conv_softmax_kernel<<<g3, 256>>>(wc, bc);

    dim3 g4(TT/K4T, CC, BB);
    out_kernel<<<g4, 256>>>(xf, out);
}

// round 3
// speedup vs baseline: 1.6486x; 1.5841x over previous
#include <cuda_runtime.h>
#include <math.h>

#define BB 2
#define CC 128
#define TT 512
#define FF 64
#define HH 32
#define DD 32

typedef unsigned long long u64;

// -------- f32x2 packed-FMA helpers (sm_103a) --------
__device__ __forceinline__ u64 pack2(float lo, float hi) {
    u64 r; asm("mov.b64 %0,{%1,%2};" : "=l"(r) : "f"(lo), "f"(hi)); return r;
}
__device__ __forceinline__ void unpack2(u64 v, float& a, float& b) {
    asm("mov.b64 {%0,%1},%2;" : "=f"(a), "=f"(b) : "l"(v));
}
__device__ __forceinline__ u64 fma2(u64 a, u64 b, u64 c) {
    u64 d; asm("fma.rn.f32x2 %0,%1,%2,%3;" : "=l"(d) : "l"(a), "l"(b), "l"(c)); return d;
}
__device__ __forceinline__ u64 pair64(unsigned lo, unsigned hi) {
    u64 r; asm("mov.b64 %0,{%1,%2};" : "=l"(r) : "r"(lo), "r"(hi)); return r;
}

// -------- scratch (device globals: allocation-free) --------
__device__ float g_xm1[BB*HH*TT*FF];   // (b,h,t,f)
__device__ float g_xf1[BB*HH*TT*FF];   // (b,h,t,f)
__device__ float g_corr[BB*HH*TT*DD];  // (b,h,t,d)
__device__ float g_w[BB*TT*DD];        // (b,t,d) softmax weights

// ============================================================
// K1 (fused both projections): out[b,h,t,f] = sum_c x[b,c,t,f]*w[c,h] + bias[h]
// thread = (b, t-pair, f); 2 t-rows per thread so each weight LDS feeds
// 4 FFMA2. Weights read as LDS.128 (2 h-pairs at once).
// grid = (128, 2): blockIdx.y selects xm/xf projection.
// ============================================================
__global__ void __launch_bounds__(256) proj_kernel(
    const float* __restrict__ xm, const float* __restrict__ xf,
    const float* __restrict__ w1, const float* __restrict__ b1,
    const float* __restrict__ w2, const float* __restrict__ b2)
{
    __shared__ __align__(16) float ws[CC*HH];   // [c][h]
    __shared__ float bs[HH];
    int which = blockIdx.y;
    const float* x    = which ? xf : xm;
    const float* w    = which ? w2 : w1;
    const float* bias = which ? b2 : b1;
    float* outg = which ? g_xf1 : g_xm1;

    int tid = threadIdx.x;
    for (int i = tid; i < CC*HH; i += 256) ws[i] = w[i];
    if (tid < HH) bs[tid] = bias[tid];
    __syncthreads();

    int f  = tid & 63;
    int tp = tid >> 6;                       // 0..3
    int bx = blockIdx.x;
    int b  = bx >> 6;
    int t  = (((bx & 63) << 2) + tp) << 1;   // even t; thread does t and t+1

    u64 acc0[16], acc1[16];
#pragma unroll
    for (int i = 0; i < 16; i++) { acc0[i] = 0ull; acc1[i] = 0ull; }

    const float* xp = x + ((size_t)b*CC*TT + t)*FF + f;

#pragma unroll 1
    for (int c0 = 0; c0 < CC; c0 += 8) {
        float va[8], vb[8];
#pragma unroll
        for (int j = 0; j < 8; j++) {
            const float* p = xp + (size_t)(c0+j)*TT*FF;
            va[j] = p[0];
            vb[j] = p[FF];
        }
#pragma unroll
        for (int j = 0; j < 8; j++) {
            u64 pa = pack2(va[j], va[j]);
            u64 pb = pack2(vb[j], vb[j]);
            const uint4* wq = (const uint4*)(ws + (c0+j)*HH);
#pragma unroll
            for (int q = 0; q < 8; q++) {
                uint4 wv = wq[q];
                u64 w01 = pair64(wv.x, wv.y);
                u64 w23 = pair64(wv.z, wv.w);
                acc0[2*q]   = fma2(pa, w01, acc0[2*q]);
                acc0[2*q+1] = fma2(pa, w23, acc0[2*q+1]);
                acc1[2*q]   = fma2(pb, w01, acc1[2*q]);
                acc1[2*q+1] = fma2(pb, w23, acc1[2*q+1]);
            }
        }
    }

#pragma unroll
    for (int q = 0; q < 16; q++) {
        float a0, a1, c0v, c1v;
        unpack2(acc0[q], a0, a1);
        unpack2(acc1[q], c0v, c1v);
        int h0 = 2*q, h1 = 2*q+1;
        float* o0 = outg + ((size_t)(b*HH+h0)*TT + t)*FF + f;
        float* o1 = outg + ((size_t)(b*HH+h1)*TT + t)*FF + f;
        o0[0]  = a0  + bs[h0];
        o0[FF] = c0v + bs[h0];
        o1[0]  = a1  + bs[h1];
        o1[FF] = c1v + bs[h1];
    }
}

// ============================================================
// K2: banded correlation (register-tiled band-GEMM) — unchanged
// corr[b,h,t,d] = sum_f xm1[b,h,t,f] * xf1[b,h,t+d-31,f]   (0-padded)
// ============================================================
#define K2T 64
#define K2S 70
__global__ void corr_kernel()
{
    __shared__ float sm[K2T*K2S];
    __shared__ float sf[(K2T+31)*K2S];

    int b = blockIdx.z, h = blockIdx.y, t0 = blockIdx.x * K2T;
    int tid = threadIdx.x;   // 128

    const float* xmp = g_xm1 + ((size_t)(b*HH+h)*TT)*FF;
    const float* xfp = g_xf1 + ((size_t)(b*HH+h)*TT)*FF;

    for (int i = tid; i < K2T*FF; i += 128) {
        int r = i >> 6, fc = i & 63;
        sm[r*K2S + fc] = xmp[(size_t)(t0+r)*FF + fc];
    }
    for (int i = tid; i < (K2T+31)*FF; i += 128) {
        int r = i / 64, fc = i & 63;
        int tt = t0 + r - 31;
        sf[r*K2S + fc] = (tt >= 0) ? xfp[(size_t)tt*FF + fc] : 0.f;
    }
    __syncthreads();

    int tl0 = (tid >> 3) << 2;
    int d0  = (tid & 7)  << 2;

    u64 acc[4][4];
#pragma unroll
    for (int i = 0; i < 4; i++)
#pragma unroll
        for (int j = 0; j < 4; j++) acc[i][j] = 0ull;

#pragma unroll 2
    for (int fcp = 0; fcp < FF/2; fcp++) {
        u64 a[4], br[7];
#pragma unroll
        for (int i = 0; i < 4; i++)
            a[i] = *(const u64*)(sm + (tl0+i)*K2S + fcp*2);
#pragma unroll
        for (int k = 0; k < 7; k++)
            br[k] = *(const u64*)(sf + (tl0+d0+k)*K2S + fcp*2);
#pragma unroll
        for (int i = 0; i < 4; i++)
#pragma unroll
            for (int j = 0; j < 4; j++)
                acc[i][j] = fma2(a[i], br[i+j], acc[i][j]);
    }

#pragma unroll
    for (int i = 0; i < 4; i++) {
        float4 v; float x0, x1;
        unpack2(acc[i][0], x0, x1); v.x = x0 + x1;
        unpack2(acc[i][1], x0, x1); v.y = x0 + x1;
        unpack2(acc[i][2], x0, x1); v.z = x0 + x1;
        unpack2(acc[i][3], x0, x1); v.w = x0 + x1;
        *(float4*)(g_corr + (((size_t)(b*HH+h)*TT + (t0+tl0+i))*DD + d0)) = v;
    }
}

// ============================================================
// K3: 5x3 conv over (t,d) reduced over h, + bias, mask, softmax over d
// block = (b, 8-t tile) -> grid 128. Stage 16 heads at once (2 phases),
// massive MLP on the staging loads, only 3 syncs total.
// ============================================================
__global__ void conv_softmax_kernel(const float* __restrict__ wc,
                                    const float* __restrict__ bc)
{
    __shared__ float sc[16][12*36];    // 16 heads x (12 t-rows x 34 d-cols, pad 36)
    __shared__ float wcs[HH*15];
    int tid = threadIdx.x;  // 256
    int b = blockIdx.y, t0 = blockIdx.x * 8;

    for (int i = tid; i < HH*15; i += 256) wcs[i] = wc[i];

    int d  = tid & 31;
    int tl = tid >> 5;     // 0..7
    float acc = 0.f;

#pragma unroll 1
    for (int ph = 0; ph < 2; ph++) {
        __syncthreads();   // protects wcs (ph=0) and sc reuse (ph=1)
        const float* cpb = g_corr + ((size_t)(b*HH + ph*16)*TT)*DD;
        for (int i = tid; i < 16*12*34; i += 256) {
            int h   = i / 408;
            int rem = i - h*408;
            int r   = rem / 34;
            int col = rem - r*34;
            int tt = t0 - 3 + r, dd = col - 1;
            float v = 0.f;
            if (tt >= 0 && tt < TT && dd >= 0 && dd < DD)
                v = cpb[(size_t)h*TT*DD + (size_t)tt*DD + dd];
            sc[h][r*36 + col] = v;
        }
        __syncthreads();
#pragma unroll 1
        for (int h = 0; h < 16; h++) {
            const float* s  = sc[h] + tl*36 + d;
            const float* wv = wcs + (ph*16 + h)*15;
#pragma unroll
            for (int kh = 0; kh < 5; kh++)
#pragma unroll
                for (int kw = 0; kw < 3; kw++)
                    acc = fmaf(s[kh*36 + kw], wv[kh*3 + kw], acc);
        }
    }

    acc += bc[0];
    int t = t0 + tl;
    if (t + d < DD - 1) acc = -1e13f;

    float m = acc;
#pragma unroll
    for (int o = 16; o; o >>= 1) m = fmaxf(m, __shfl_xor_sync(0xffffffffu, m, o));
    float e = expf(acc - m);
    float s = e;
#pragma unroll
    for (int o = 16; o; o >>= 1) s += __shfl_xor_sync(0xffffffffu, s, o);

    g_w[((size_t)b*TT + t)*DD + d] = e / s;
}

// ============================================================
// K4: out[b,c,t,f] = sum_d w[b,t,d] * xf[b,c,t+d-31,f]
// block = (64-t tile, c, b), 128 threads: thread = (f-quad, 8 t).
// One LDS.128 of x feeds 16 FFMA2 (8 t x 2 f-pairs).
// ============================================================
#define K4T 64
__global__ void out_kernel(const float* __restrict__ xf, float* __restrict__ out)
{
    __shared__ __align__(16) float sx[(K4T+31)*FF];  // xf rows t0-31 .. t0+63
    __shared__ u64 swd[K4T*DD];                      // duplicated weights (w,w)

    int b = blockIdx.z, c = blockIdx.y, t0 = blockIdx.x * K4T;
    int tid = threadIdx.x;  // 128

    const float* xp = xf + ((size_t)(b*CC + c)*TT)*FF;
    for (int i = tid; i < (K4T+31)*FF; i += 128) {
        int r = i >> 6;
        int tt = t0 + r - 31;
        sx[i] = (tt >= 0) ? xp[(size_t)tt*FF + (i & 63)] : 0.f;
    }
    const float* wp = g_w + ((size_t)b*TT + t0)*DD;
    for (int i = tid; i < K4T*DD; i += 128) {
        float v = wp[i];
        swd[i] = pack2(v, v);
    }
    __syncthreads();

    int fq = tid & 15;           // f-quad: f = 4*fq .. 4*fq+3
    int tb = (tid >> 4) * 8;     // t_local range [tb, tb+8)

    u64 acc[8][2];
#pragma unroll
    for (int i = 0; i < 8; i++) { acc[i][0] = 0ull; acc[i][1] = 0ull; }

#pragma unroll 1
    for (int r = tb; r < tb + 39; r++) {
        ulonglong2 xv = *(const ulonglong2*)(sx + r*FF + fq*4);
#pragma unroll
        for (int i = 0; i < 8; i++) {
            int dd = r - tb - i;
            if (dd >= 0 && dd < DD) {
                u64 wv = swd[(tb+i)*DD + dd];
                acc[i][0] = fma2(xv.x, wv, acc[i][0]);
                acc[i][1] = fma2(xv.y, wv, acc[i][1]);
            }
        }
    }

    float* op = out + ((size_t)(b*CC + c)*TT + (t0 + tb))*FF + fq*4;
#pragma unroll
    for (int i = 0; i < 8; i++) {
        float4 v;
        unpack2(acc[i][0], v.x, v.y);
        unpack2(acc[i][1], v.z, v.w);
        *(float4*)(op + (size_t)i*FF) = v;
    }
}

// ============================================================
extern "C" void kernel_launch(void* const* d_in, const int* in_sizes, int n_in,
                              void* d_out, int out_size)
{
    const float* xm = (const float*)d_in[0];
    const float* xf = (const float*)d_in[1];
    const float* w1 = (const float*)d_in[2];
    const float* b1 = (const float*)d_in[3];
    const float* w2 = (const float*)d_in[4];
    const float* b2 = (const float*)d_in[5];
    const float* wc = (const float*)d_in[6];
    const float* bc = (const float*)d_in[7];
    float* out = (float*)d_out;

    (void)in_sizes; (void)n_in; (void)out_size;

    proj_kernel<<<dim3(128, 2), 256>>>(xm, xf, w1, b1, w2, b2);

    dim3 g2(TT/K2T, HH, BB);
    corr_kernel<<<g2, 128>>>();

    dim3 g3(TT/8, BB);
    conv_softmax_kernel<<<g3, 256>>>(wc, bc);

    dim3 g4(TT/K4T, CC, BB);
    out_kernel<<<g4, 128>>>(xf, out);
}

// round 4
// speedup vs baseline: 1.9149x; 1.1616x over previous
#include <cuda_runtime.h>
#include <math.h>

#define BB 2
#define CC 128
#define TT 512
#define FF 64
#define HH 32
#define DD 32

typedef unsigned long long u64;

// -------- f32x2 packed-FMA helpers (sm_103a) --------
__device__ __forceinline__ u64 pack2(float lo, float hi) {
    u64 r; asm("mov.b64 %0,{%1,%2};" : "=l"(r) : "f"(lo), "f"(hi)); return r;
}
__device__ __forceinline__ void unpack2(u64 v, float& a, float& b) {
    asm("mov.b64 {%0,%1},%2;" : "=f"(a), "=f"(b) : "l"(v));
}
__device__ __forceinline__ u64 fma2(u64 a, u64 b, u64 c) {
    u64 d; asm("fma.rn.f32x2 %0,%1,%2,%3;" : "=l"(d) : "l"(a), "l"(b), "l"(c)); return d;
}

// -------- scratch (device globals: allocation-free) --------
__device__ float g_xm1[BB*HH*TT*FF];   // (b,h,t,f)
__device__ float g_xf1[BB*HH*TT*FF];   // (b,h,t,f)
__device__ float g_corr[BB*HH*TT*DD];  // (b,h,t,d)
__device__ float g_w[BB*TT*DD];        // (b,t,d) softmax weights

// ============================================================
// K1 (fused both projections): out[b,h,t,f] = sum_c x[b,c,t,f]*w[c,h] + bias[h]
// thread = (b, t-pair, f); 2 t-rows per thread. Weights read as
// ulonglong2 (LDS.128 -> two u64 h-pairs, no repack movs).
// ============================================================
__global__ void __launch_bounds__(256) proj_kernel(
    const float* __restrict__ xm, const float* __restrict__ xf,
    const float* __restrict__ w1, const float* __restrict__ b1,
    const float* __restrict__ w2, const float* __restrict__ b2)
{
    __shared__ __align__(16) float ws[CC*HH];   // [c][h]
    __shared__ float bs[HH];
    int which = blockIdx.y;
    const float* x    = which ? xf : xm;
    const float* w    = which ? w2 : w1;
    const float* bias = which ? b2 : b1;
    float* outg = which ? g_xf1 : g_xm1;

    int tid = threadIdx.x;
    for (int i = tid; i < CC*HH; i += 256) ws[i] = w[i];
    if (tid < HH) bs[tid] = bias[tid];
    __syncthreads();

    int f  = tid & 63;
    int tp = tid >> 6;                       // 0..3
    int bx = blockIdx.x;
    int b  = bx >> 6;
    int t  = (((bx & 63) << 2) + tp) << 1;   // even t; thread does t and t+1

    u64 acc0[16], acc1[16];
#pragma unroll
    for (int i = 0; i < 16; i++) { acc0[i] = 0ull; acc1[i] = 0ull; }

    const float* xp = x + ((size_t)b*CC*TT + t)*FF + f;

#pragma unroll 1
    for (int c0 = 0; c0 < CC; c0 += 8) {
        float va[8], vb[8];
#pragma unroll
        for (int j = 0; j < 8; j++) {
            const float* p = xp + (size_t)(c0+j)*TT*FF;
            va[j] = p[0];
            vb[j] = p[FF];
        }
#pragma unroll
        for (int j = 0; j < 8; j++) {
            u64 pa = pack2(va[j], va[j]);
            u64 pb = pack2(vb[j], vb[j]);
            const ulonglong2* wq = (const ulonglong2*)(ws + (c0+j)*HH);
#pragma unroll
            for (int q = 0; q < 8; q++) {
                ulonglong2 wv = wq[q];
                acc0[2*q]   = fma2(pa, wv.x, acc0[2*q]);
                acc0[2*q+1] = fma2(pa, wv.y, acc0[2*q+1]);
                acc1[2*q]   = fma2(pb, wv.x, acc1[2*q]);
                acc1[2*q+1] = fma2(pb, wv.y, acc1[2*q+1]);
            }
        }
    }

#pragma unroll
    for (int q = 0; q < 16; q++) {
        float a0, a1, c0v, c1v;
        unpack2(acc0[q], a0, a1);
        unpack2(acc1[q], c0v, c1v);
        int h0 = 2*q, h1 = 2*q+1;
        float* o0 = outg + ((size_t)(b*HH+h0)*TT + t)*FF + f;
        float* o1 = outg + ((size_t)(b*HH+h1)*TT + t)*FF + f;
        o0[0]  = a0  + bs[h0];
        o0[FF] = c0v + bs[h0];
        o1[0]  = a1  + bs[h1];
        o1[FF] = c1v + bs[h1];
    }
}

// ============================================================
// K2: banded correlation (register-tiled band-GEMM)
// corr[b,h,t,d] = sum_f xm1[b,h,t,f] * xf1[b,h,t+d-31,f]   (0-padded)
// 256 threads (was 128): grid was latency/occupancy-limited.
// Thread tile: 2 t x 4 d, f32x2 over f-pairs.
// ============================================================
#define K2T 64
#define K2S 70
__global__ void __launch_bounds__(256) corr_kernel()
{
    __shared__ float sm[K2T*K2S];
    __shared__ float sf[(K2T+31)*K2S];

    int b = blockIdx.z, h = blockIdx.y, t0 = blockIdx.x * K2T;
    int tid = threadIdx.x;   // 256

    const float* xmp = g_xm1 + ((size_t)(b*HH+h)*TT)*FF;
    const float* xfp = g_xf1 + ((size_t)(b*HH+h)*TT)*FF;

    for (int i = tid; i < K2T*FF; i += 256) {
        int r = i >> 6, fc = i & 63;
        sm[r*K2S + fc] = xmp[(size_t)(t0+r)*FF + fc];
    }
    for (int i = tid; i < (K2T+31)*FF; i += 256) {
        int r = i >> 6, fc = i & 63;
        int tt = t0 + r - 31;
        sf[r*K2S + fc] = (tt >= 0) ? xfp[(size_t)tt*FF + fc] : 0.f;
    }
    __syncthreads();

    int tl0 = (tid >> 3) << 1;   // 0,2,...,62
    int d0  = (tid & 7)  << 2;   // 0,4,...,28

    u64 acc[2][4];
#pragma unroll
    for (int i = 0; i < 2; i++)
#pragma unroll
        for (int j = 0; j < 4; j++) acc[i][j] = 0ull;

#pragma unroll 4
    for (int fcp = 0; fcp < FF/2; fcp++) {
        u64 a[2], br[5];
#pragma unroll
        for (int i = 0; i < 2; i++)
            a[i] = *(const u64*)(sm + (tl0+i)*K2S + fcp*2);
#pragma unroll
        for (int k = 0; k < 5; k++)
            br[k] = *(const u64*)(sf + (tl0+d0+k)*K2S + fcp*2);
#pragma unroll
        for (int i = 0; i < 2; i++)
#pragma unroll
            for (int j = 0; j < 4; j++)
                acc[i][j] = fma2(a[i], br[i+j], acc[i][j]);
    }

#pragma unroll
    for (int i = 0; i < 2; i++) {
        float4 v; float x0, x1;
        unpack2(acc[i][0], x0, x1); v.x = x0 + x1;
        unpack2(acc[i][1], x0, x1); v.y = x0 + x1;
        unpack2(acc[i][2], x0, x1); v.z = x0 + x1;
        unpack2(acc[i][3], x0, x1); v.w = x0 + x1;
        *(float4*)(g_corr + (((size_t)(b*HH+h)*TT + (t0+tl0+i))*DD + d0)) = v;
    }
}

// ============================================================
// K3: 5x3 conv over (t,d) reduced over h, + bias, mask, softmax over d
// block = (b, 8-t tile) -> grid 128. Stage 16 heads at once (2 phases).
// ============================================================
__global__ void conv_softmax_kernel(const float* __restrict__ wc,
                                    const float* __restrict__ bc)
{
    __shared__ float sc[16][12*36];
    __shared__ float wcs[HH*15];
    int tid = threadIdx.x;  // 256
    int b = blockIdx.y, t0 = blockIdx.x * 8;

    for (int i = tid; i < HH*15; i += 256) wcs[i] = wc[i];

    int d  = tid & 31;
    int tl = tid >> 5;
    float acc = 0.f;

#pragma unroll 1
    for (int ph = 0; ph < 2; ph++) {
        __syncthreads();
        const float* cpb = g_corr + ((size_t)(b*HH + ph*16)*TT)*DD;
        for (int i = tid; i < 16*12*34; i += 256) {
            int h   = i / 408;
            int rem = i - h*408;
            int r   = rem / 34;
            int col = rem - r*34;
            int tt = t0 - 3 + r, dd = col - 1;
            float v = 0.f;
            if (tt >= 0 && tt < TT && dd >= 0 && dd < DD)
                v = cpb[(size_t)h*TT*DD + (size_t)tt*DD + dd];
            sc[h][r*36 + col] = v;
        }
        __syncthreads();
#pragma unroll 1
        for (int h = 0; h < 16; h++) {
            const float* s  = sc[h] + tl*36 + d;
            const float* wv = wcs + (ph*16 + h)*15;
#pragma unroll
            for (int kh = 0; kh < 5; kh++)
#pragma unroll
                for (int kw = 0; kw < 3; kw++)
                    acc = fmaf(s[kh*36 + kw], wv[kh*3 + kw], acc);
        }
    }

    acc += bc[0];
    int t = t0 + tl;
    if (t + d < DD - 1) acc = -1e13f;

    float m = acc;
#pragma unroll
    for (int o = 16; o; o >>= 1) m = fmaxf(m, __shfl_xor_sync(0xffffffffu, m, o));
    float e = expf(acc - m);
    float s = e;
#pragma unroll
    for (int o = 16; o; o >>= 1) s += __shfl_xor_sync(0xffffffffu, s, o);

    g_w[((size_t)b*TT + t)*DD + d] = e / s;
}

// ============================================================
// K4: out[b,c,t,f] = sum_d w[b,t,d] * xf[b,c,t+d-31,f]
// 256 threads: thread = (f-quad 0..15, t-group 0..15 of 4 t).
// Weights duplicated (w,w) AND zero-padded over d in [-3,34]:
// inner loop has ZERO predicates/bounds -> pure LDS+FFMA2.
// ============================================================
#define K4T 64
#define K4W 38   // padded weight width: d in [-3, 34]
__global__ void __launch_bounds__(256) out_kernel(const float* __restrict__ xf,
                                                  float* __restrict__ out)
{
    __shared__ __align__(16) float sx[(K4T+31)*FF];  // 24320 B
    __shared__ u64 swd[K4T*K4W];                     // 19456 B

    int b = blockIdx.z, c = blockIdx.y, t0 = blockIdx.x * K4T;
    int tid = threadIdx.x;  // 256

    const float* xp = xf + ((size_t)(b*CC + c)*TT)*FF;
    for (int i = tid; i < (K4T+31)*FF; i += 256) {
        int r = i >> 6;
        int tt = t0 + r - 31;
        sx[i] = (tt >= 0) ? xp[(size_t)tt*FF + (i & 63)] : 0.f;
    }
    const float* wp = g_w + ((size_t)b*TT + t0)*DD;
    for (int i = tid; i < K4T*K4W; i += 256) {
        int tl = i / K4W, j = i - tl*K4W;
        int dd = j - 3;
        float v = (dd >= 0 && dd < DD) ? wp[tl*DD + dd] : 0.f;
        swd[i] = pack2(v, v);
    }
    __syncthreads();

    int fq = tid & 15;            // f = 4*fq .. 4*fq+3
    int tb = (tid >> 4) << 2;     // t_local base: 0,4,...,60

    u64 acc[4][2];
#pragma unroll
    for (int i = 0; i < 4; i++) { acc[i][0] = 0ull; acc[i][1] = 0ull; }

    const float* xrow = sx + tb*FF + fq*4;
    const u64* w0 = swd + (tb+0)*K4W + 3;   // j = rl + 3 - i + i*K4W pattern
    const u64* w1 = swd + (tb+1)*K4W + 2;
    const u64* w2 = swd + (tb+2)*K4W + 1;
    const u64* w3 = swd + (tb+3)*K4W + 0;

#pragma unroll 5
    for (int rl = 0; rl < 35; rl++) {
        ulonglong2 xv = *(const ulonglong2*)(xrow + rl*FF);
        u64 a0 = w0[rl], a1 = w1[rl], a2 = w2[rl], a3 = w3[rl];
        acc[0][0] = fma2(xv.x, a0, acc[0][0]);
        acc[0][1] = fma2(xv.y, a0, acc[0][1]);
        acc[1][0] = fma2(xv.x, a1, acc[1][0]);
        acc[1][1] = fma2(xv.y, a1, acc[1][1]);
        acc[2][0] = fma2(xv.x, a2, acc[2][0]);
        acc[2][1] = fma2(xv.y, a2, acc[2][1]);
        acc[3][0] = fma2(xv.x, a3, acc[3][0]);
        acc[3][1] = fma2(xv.y, a3, acc[3][1]);
    }

    float* op = out + ((size_t)(b*CC + c)*TT + (t0 + tb))*FF + fq*4;
#pragma unroll
    for (int i = 0; i < 4; i++) {
        float4 v;
        unpack2(acc[i][0], v.x, v.y);
        unpack2(acc[i][1], v.z, v.w);
        *(float4*)(op + (size_t)i*FF) = v;
    }
}

// ============================================================
extern "C" void kernel_launch(void* const* d_in, const int* in_sizes, int n_in,
                              void* d_out, int out_size)
{
    const float* xm = (const float*)d_in[0];
    const float* xf = (const float*)d_in[1];
    const float* w1 = (const float*)d_in[2];
    const float* b1 = (const float*)d_in[3];
    const float* w2 = (const float*)d_in[4];
    const float* b2 = (const float*)d_in[5];
    const float* wc = (const float*)d_in[6];
    const float* bc = (const float*)d_in[7];
    float* out = (float*)d_out;

    (void)in_sizes; (void)n_in; (void)out_size;

    proj_kernel<<<dim3(128, 2), 256>>>(xm, xf, w1, b1, w2, b2);

    dim3 g2(TT/K2T, HH, BB);
    corr_kernel<<<g2, 256>>>();

    dim3 g3(TT/8, BB);
    conv_softmax_kernel<<<g3, 256>>>(wc, bc);

    dim3 g4(TT/K4T, CC, BB);
    out_kernel<<<g4, 256>>>(xf, out);
}